// round 3
// baseline (speedup 1.0000x reference)
#include <cuda_runtime.h>

#define NN 100000
#define NE 3200000
#define NT (NE + NN)   // edges + self-loops
#define HD 64

// ---- scratch (allocation-free rule: __device__ globals) ----
__device__ __align__(16) int   g_src[NT];
__device__ __align__(16) int   g_dst[NT];
__device__ __align__(16) float g_norm[NT];
__device__ __align__(16) float g_deg[NN];
__device__ __align__(16) float g_dis[NN];
__device__ __align__(16) float g_h [NN * HD];   // scatter destination / activations
__device__ __align__(16) float g_hw[NN * HD];   // gather source (x@W, h@W)
__device__ __align__(16) float g_hw3[NN];       // layer-3 transformed (1 col)

// ---------------- graph preprocessing ----------------
__global__ void k_init_nodes() {
    int i = blockIdx.x * blockDim.x + threadIdx.x;
    if (i >= NN) return;
    g_deg[i] = 1.0f;           // self-loop contribution
    g_src[NE + i] = i;
    g_dst[NE + i] = i;
}

// edge_index is int32
__global__ void k_edges(const int* __restrict__ ei) {
    int e = blockIdx.x * blockDim.x + threadIdx.x;
    if (e >= NE) return;
    int s = ei[e];
    int d = ei[NE + e];
    g_src[e] = s;
    g_dst[e] = d;
    atomicAdd(&g_deg[d], 1.0f);
}

__global__ void k_dis() {
    int i = blockIdx.x * blockDim.x + threadIdx.x;
    if (i >= NN) return;
    g_dis[i] = rsqrtf(g_deg[i]);
}

__global__ void k_norm() {
    int e = blockIdx.x * blockDim.x + threadIdx.x;
    if (e >= NT) return;
    g_norm[e] = g_dis[g_src[e]] * g_dis[g_dst[e]];
}

// ---------------- dense transforms ----------------
// hw = x @ W1   (x: [NN,5], W1: [5,64])
__global__ void k_gemm1(const float* __restrict__ x, const float* __restrict__ W1) {
    __shared__ float sW[5 * HD];                     // 320 floats
    int tid = threadIdx.x;                           // 256 threads
    sW[tid] = W1[tid];                               // 0..255
    if (tid < 5 * HD - 256) sW[tid + 256] = W1[tid + 256];  // 256..319
    __syncthreads();
    int node = blockIdx.x * 4 + (tid >> 6);
    int c = tid & 63;
    if (node >= NN) return;
    float acc = 0.f;
    #pragma unroll
    for (int k = 0; k < 5; k++)
        acc += x[node * 5 + k] * sW[k * HD + c];
    g_hw[node * HD + c] = acc;
}

// hw = h @ W2   (h: [NN,64], W2: [64,64]); block handles 8 nodes
__global__ void k_gemm2(const float* __restrict__ W2) {
    __shared__ float sW[HD][HD];
    __shared__ float sh[8][HD];
    int tx = threadIdx.x;        // 0..63 (out col)
    int ty = threadIdx.y;        // 0..7  (node in block)
    int tid = ty * HD + tx;      // 0..511
    #pragma unroll
    for (int i = 0; i < 8; i++) {
        int idx = tid + i * 512;
        sW[idx >> 6][idx & 63] = W2[idx];
    }
    int node = blockIdx.x * 8 + ty;
    sh[ty][tx] = (node < NN) ? g_h[node * HD + tx] : 0.f;
    __syncthreads();
    if (node >= NN) return;
    float acc = 0.f;
    #pragma unroll
    for (int k = 0; k < HD; k++)
        acc += sh[ty][k] * sW[k][tx];
    g_hw[node * HD + tx] = acc;
}

// hw3 = h @ W3  (W3: [64,1]); one warp per node
__global__ void k_gemm3(const float* __restrict__ W3) {
    __shared__ float sW[HD];
    int tid = threadIdx.x;
    if (tid < HD) sW[tid] = W3[tid];
    __syncthreads();
    int lane = tid & 31;
    int node = blockIdx.x * 8 + (tid >> 5);
    if (node >= NN) return;
    const float* row = g_h + (size_t)node * HD;
    float s = row[lane] * sW[lane] + row[lane + 32] * sW[lane + 32];
    #pragma unroll
    for (int off = 16; off > 0; off >>= 1)
        s += __shfl_down_sync(0xFFFFFFFFu, s, off);
    if (lane == 0) g_hw3[node] = s;
}

// ---------------- scatter (message passing) ----------------
__global__ void k_zero_h() {
    int i = blockIdx.x * blockDim.x + threadIdx.x;   // over NN*HD/4
    if (i >= NN * HD / 4) return;
    reinterpret_cast<float4*>(g_h)[i] = make_float4(0.f, 0.f, 0.f, 0.f);
}

// 16 lanes per edge; each lane moves a float4 via vectorized red
__global__ void k_scatter64() {
    long long t = (long long)blockIdx.x * blockDim.x + threadIdx.x;
    int e = (int)(t >> 4);
    if (e >= NT) return;
    int j = ((int)t & 15) << 2;            // float offset 0..60
    int s = g_src[e];
    int d = g_dst[e];
    float nm = g_norm[e];
    float4 v = *reinterpret_cast<const float4*>(g_hw + (size_t)s * HD + j);
    float a = v.x * nm, b = v.y * nm, c = v.z * nm, w = v.w * nm;
    float* p = g_h + (size_t)d * HD + j;
    asm volatile("red.global.add.v4.f32 [%0], {%1,%2,%3,%4};"
                 :: "l"(p), "f"(a), "f"(b), "f"(c), "f"(w) : "memory");
}

__global__ void k_bias_relu(const float* __restrict__ b) {
    int i = blockIdx.x * blockDim.x + threadIdx.x;
    if (i >= NN * HD) return;
    g_h[i] = fmaxf(g_h[i] + b[i & 63], 0.f);
}

__global__ void k_out_init(float* __restrict__ out, const float* __restrict__ b3) {
    int i = blockIdx.x * blockDim.x + threadIdx.x;
    if (i >= NN) return;
    out[i] = b3[0];
}

__global__ void k_scatter1(float* __restrict__ out) {
    int e = blockIdx.x * blockDim.x + threadIdx.x;
    if (e >= NT) return;
    atomicAdd(&out[g_dst[e]], g_norm[e] * g_hw3[g_src[e]]);
}

// ---------------- launch ----------------
extern "C" void kernel_launch(void* const* d_in, const int* in_sizes, int n_in,
                              void* d_out, int out_size) {
    const float* x  = (const float*)d_in[0];
    const int*   ei = (const int*)d_in[1];
    const float* W1 = (const float*)d_in[2];
    const float* b1 = (const float*)d_in[3];
    const float* W2 = (const float*)d_in[4];
    const float* b2 = (const float*)d_in[5];
    const float* W3 = (const float*)d_in[6];
    const float* b3 = (const float*)d_in[7];
    float* out = (float*)d_out;

    const int TB = 256;
    // --- norm build ---
    k_init_nodes<<<(NN + TB - 1) / TB, TB>>>();
    k_edges<<<(NE + TB - 1) / TB, TB>>>(ei);
    k_dis<<<(NN + TB - 1) / TB, TB>>>();
    k_norm<<<(NT + TB - 1) / TB, TB>>>();

    // --- layer 1 ---
    k_gemm1<<<(NN + 3) / 4, TB>>>(x, W1);
    k_zero_h<<<(NN * HD / 4 + TB - 1) / TB, TB>>>();
    k_scatter64<<<(int)(((long long)NT * 16 + TB - 1) / TB), TB>>>();
    k_bias_relu<<<(NN * HD + TB - 1) / TB, TB>>>(b1);

    // --- layer 2 ---
    k_gemm2<<<(NN + 7) / 8, dim3(64, 8)>>>(W2);
    k_zero_h<<<(NN * HD / 4 + TB - 1) / TB, TB>>>();
    k_scatter64<<<(int)(((long long)NT * 16 + TB - 1) / TB), TB>>>();
    k_bias_relu<<<(NN * HD + TB - 1) / TB, TB>>>(b2);

    // --- layer 3 ---
    k_gemm3<<<(NN + 7) / 8, TB>>>(W3);
    k_out_init<<<(NN + TB - 1) / TB, TB>>>(out, b3);
    k_scatter1<<<(NT + TB - 1) / TB, TB>>>(out);
}

// round 4
// speedup vs baseline: 1.9254x; 1.9254x over previous
#include <cuda_runtime.h>

#define NN 100000
#define NE 3200000
#define HD 64
#define SCAN_B 1024
#define NBLK ((NN + SCAN_B - 1) / SCAN_B)   // 98

// ---- scratch (__device__ globals; no allocation allowed) ----
__device__ __align__(16) int   g_hist[NN];        // in-degree (excl. self-loop)
__device__ __align__(16) int   g_off[NN + 1];     // CSR offsets
__device__ __align__(16) int   g_cursor[NN];      // fill cursors
__device__ __align__(16) int   g_bsum[NBLK];      // scan block sums
__device__ __align__(16) int   g_csr[NE];         // CSR src lists (by dst)
__device__ __align__(16) float g_dis[NN];         // deg^{-1/2}
__device__ __align__(16) float g_h [NN * HD];     // activations
__device__ __align__(16) float g_hw[NN * HD];     // dis * (h @ W)
__device__ __align__(16) float g_hw3[NN];         // layer-3 column

// ================= graph preprocessing =================
__global__ void k_zero_hist() {
    int i = blockIdx.x * blockDim.x + threadIdx.x;
    if (i < NN) g_hist[i] = 0;
}

__global__ void k_hist(const int* __restrict__ ei) {
    int e = blockIdx.x * blockDim.x + threadIdx.x;
    if (e >= NE) return;
    atomicAdd(&g_hist[ei[NE + e]], 1);
}

// per-block exclusive scan of hist -> off, block totals -> bsum
__global__ void k_scan1() {
    __shared__ int s[SCAN_B];
    int t = threadIdx.x;
    int i = blockIdx.x * SCAN_B + t;
    int v = (i < NN) ? g_hist[i] : 0;
    s[t] = v;
    __syncthreads();
    #pragma unroll
    for (int off = 1; off < SCAN_B; off <<= 1) {
        int add = (t >= off) ? s[t - off] : 0;
        __syncthreads();
        s[t] += add;
        __syncthreads();
    }
    if (i < NN) g_off[i] = s[t] - v;            // exclusive
    if (t == SCAN_B - 1) g_bsum[blockIdx.x] = s[t];
}

// scan the 98 block sums (one block)
__global__ void k_scan2() {
    __shared__ int s[128];
    int t = threadIdx.x;
    int v = (t < NBLK) ? g_bsum[t] : 0;
    s[t] = v;
    __syncthreads();
    #pragma unroll
    for (int off = 1; off < 128; off <<= 1) {
        int add = (t >= off) ? s[t - off] : 0;
        __syncthreads();
        s[t] += add;
        __syncthreads();
    }
    if (t < NBLK) g_bsum[t] = s[t] - v;         // exclusive
}

// finalize offsets, cursors, dis
__global__ void k_scan3() {
    int i = blockIdx.x * blockDim.x + threadIdx.x;
    if (i >= NN) return;
    int o = g_off[i] + g_bsum[i >> 10];
    g_off[i] = o;
    g_cursor[i] = o;
    g_dis[i] = rsqrtf(1.0f + (float)g_hist[i]);  // +1 self-loop
    if (i == 0) g_off[NN] = NE;
}

__global__ void k_fill(const int* __restrict__ ei) {
    int e = blockIdx.x * blockDim.x + threadIdx.x;
    if (e >= NE) return;
    int s = ei[e];
    int d = ei[NE + e];
    int pos = atomicAdd(&g_cursor[d], 1);
    g_csr[pos] = s;
}

// ================= dense transforms (dis pre-scaled) =================
// hw = dis ⊙ (x @ W1)
__global__ void k_gemm1(const float* __restrict__ x, const float* __restrict__ W1) {
    __shared__ float sW[5 * HD];
    int tid = threadIdx.x;                       // 256
    sW[tid] = W1[tid];
    if (tid < 5 * HD - 256) sW[tid + 256] = W1[tid + 256];
    __syncthreads();
    int node = blockIdx.x * 4 + (tid >> 6);
    int c = tid & 63;
    if (node >= NN) return;
    float acc = 0.f;
    #pragma unroll
    for (int k = 0; k < 5; k++)
        acc += x[node * 5 + k] * sW[k * HD + c];
    g_hw[node * HD + c] = acc * g_dis[node];
}

// hw = dis ⊙ (h @ W2); 16 nodes/block, 4 cols/thread
__global__ void k_gemm2(const float* __restrict__ W2) {
    __shared__ float sW[HD][HD];
    __shared__ float sh[16][HD];
    int tx = threadIdx.x;        // 0..15 (col group)
    int ty = threadIdx.y;        // 0..15 (node)
    int tid = ty * 16 + tx;      // 0..255
    #pragma unroll
    for (int i = 0; i < 16; i++) {
        int idx = tid + i * 256;
        sW[idx >> 6][idx & 63] = W2[idx];
    }
    int node = blockIdx.x * 16 + ty;
    const float* hrow = g_h + (size_t)node * HD;
    #pragma unroll
    for (int i = 0; i < 4; i++)
        sh[ty][tx + i * 16] = (node < NN) ? hrow[tx + i * 16] : 0.f;
    __syncthreads();
    if (node >= NN) return;
    float4 acc = make_float4(0.f, 0.f, 0.f, 0.f);
    #pragma unroll
    for (int k = 0; k < HD; k++) {
        float a = sh[ty][k];
        float4 w = *reinterpret_cast<const float4*>(&sW[k][tx * 4]);
        acc.x += a * w.x; acc.y += a * w.y;
        acc.z += a * w.z; acc.w += a * w.w;
    }
    float dn = g_dis[node];
    acc.x *= dn; acc.y *= dn; acc.z *= dn; acc.w *= dn;
    *reinterpret_cast<float4*>(g_hw + (size_t)node * HD + tx * 4) = acc;
}

// hw3 = dis ⊙ (h @ W3); one warp per node
__global__ void k_gemm3(const float* __restrict__ W3) {
    __shared__ float sW[HD];
    int tid = threadIdx.x;
    if (tid < HD) sW[tid] = W3[tid];
    __syncthreads();
    int lane = tid & 31;
    int node = blockIdx.x * 8 + (tid >> 5);
    if (node >= NN) return;
    const float* row = g_h + (size_t)node * HD;
    float s = row[lane] * sW[lane] + row[lane + 32] * sW[lane + 32];
    #pragma unroll
    for (int off = 16; off > 0; off >>= 1)
        s += __shfl_down_sync(0xFFFFFFFFu, s, off);
    if (lane == 0) g_hw3[node] = s * g_dis[node];
}

// ================= gather (message passing) =================
// one warp per node; lane owns 2 floats; h[d] = relu(dis[d]*(hw[d]+Σ hw[src]) + b)
__global__ void k_gather64(const float* __restrict__ bias) {
    int lane = threadIdx.x & 31;
    int node = blockIdx.x * 8 + (threadIdx.x >> 5);
    if (node >= NN) return;
    int start = g_off[node];
    int end   = g_off[node + 1];
    float2 acc = *reinterpret_cast<const float2*>(g_hw + (size_t)node * HD + 2 * lane); // self-loop
    for (int base = start; base < end; base += 32) {
        int idx = (base + lane < end) ? g_csr[base + lane] : 0;
        int m = end - base; if (m > 32) m = 32;
        #pragma unroll 4
        for (int j = 0; j < m; j++) {
            int s = __shfl_sync(0xFFFFFFFFu, idx, j);
            float2 v = *reinterpret_cast<const float2*>(g_hw + (size_t)s * HD + 2 * lane);
            acc.x += v.x; acc.y += v.y;
        }
    }
    float dn = g_dis[node];
    float2 r;
    r.x = fmaxf(dn * acc.x + bias[2 * lane], 0.f);
    r.y = fmaxf(dn * acc.y + bias[2 * lane + 1], 0.f);
    *reinterpret_cast<float2*>(g_h + (size_t)node * HD + 2 * lane) = r;
}

// layer 3: one warp per node, lanes stride edges; out = dis*(hw3[d]+Σ hw3[src]) + b3
__global__ void k_gather1(float* __restrict__ out, const float* __restrict__ b3) {
    int lane = threadIdx.x & 31;
    int node = blockIdx.x * 8 + (threadIdx.x >> 5);
    if (node >= NN) return;
    int start = g_off[node];
    int end   = g_off[node + 1];
    float acc = 0.f;
    for (int i = start + lane; i < end; i += 32)
        acc += g_hw3[g_csr[i]];
    #pragma unroll
    for (int off = 16; off > 0; off >>= 1)
        acc += __shfl_down_sync(0xFFFFFFFFu, acc, off);
    if (lane == 0)
        out[node] = g_dis[node] * (acc + g_hw3[node]) + b3[0];
}

// ================= launch =================
extern "C" void kernel_launch(void* const* d_in, const int* in_sizes, int n_in,
                              void* d_out, int out_size) {
    const float* x  = (const float*)d_in[0];
    const int*   ei = (const int*)d_in[1];
    const float* W1 = (const float*)d_in[2];
    const float* b1 = (const float*)d_in[3];
    const float* W2 = (const float*)d_in[4];
    const float* b2 = (const float*)d_in[5];
    const float* W3 = (const float*)d_in[6];
    const float* b3 = (const float*)d_in[7];
    float* out = (float*)d_out;

    const int TB = 256;
    // --- CSR + norm build ---
    k_zero_hist<<<(NN + TB - 1) / TB, TB>>>();
    k_hist<<<(NE + TB - 1) / TB, TB>>>(ei);
    k_scan1<<<NBLK, SCAN_B>>>();
    k_scan2<<<1, 128>>>();
    k_scan3<<<(NN + TB - 1) / TB, TB>>>();
    k_fill<<<(NE + TB - 1) / TB, TB>>>(ei);

    // --- layer 1 ---
    k_gemm1<<<(NN + 3) / 4, TB>>>(x, W1);
    k_gather64<<<(NN + 7) / 8, TB>>>(b1);

    // --- layer 2 ---
    k_gemm2<<<(NN + 15) / 16, dim3(16, 16)>>>(W2);
    k_gather64<<<(NN + 7) / 8, TB>>>(b2);

    // --- layer 3 ---
    k_gemm3<<<(NN + 7) / 8, TB>>>(W3);
    k_gather1<<<(NN + 7) / 8, TB>>>(out, b3);
}

// round 5
// speedup vs baseline: 1.9842x; 1.0305x over previous
#include <cuda_runtime.h>
#include <cuda_fp16.h>

#define NN 100000
#define NE 3200000
#define HD 64
#define SCAN_B 1024
#define NBLK ((NN + SCAN_B - 1) / SCAN_B)   // 98

// ---- scratch (__device__ globals; no allocation allowed) ----
__device__ __align__(16) int    g_hist[NN];        // in-degree (excl. self-loop)
__device__ __align__(16) int    g_off[NN + 1];     // CSR offsets
__device__ __align__(16) int    g_cursor[NN];      // fill cursors
__device__ __align__(16) int    g_bsum[NBLK];      // scan block sums
__device__ __align__(16) int    g_csr[NE];         // CSR src lists (by dst)
__device__ __align__(16) float  g_dis[NN];         // deg^{-1/2}
__device__ __align__(16) float  g_h [NN * HD];     // activations (fp32)
__device__ __align__(16) __half g_hw[NN * HD];     // dis * (h @ W), fp16 payload
__device__ __align__(16) float  g_hw3[NN];         // layer-3 column (fp32)

// ================= graph preprocessing =================
__global__ void k_zero_hist() {
    int i = blockIdx.x * blockDim.x + threadIdx.x;
    if (i < NN) g_hist[i] = 0;
}

__global__ void k_hist(const int* __restrict__ ei) {
    int e = blockIdx.x * blockDim.x + threadIdx.x;
    if (e >= NE) return;
    atomicAdd(&g_hist[ei[NE + e]], 1);
}

// per-block exclusive scan of hist -> off, block totals -> bsum
__global__ void k_scan1() {
    __shared__ int s[SCAN_B];
    int t = threadIdx.x;
    int i = blockIdx.x * SCAN_B + t;
    int v = (i < NN) ? g_hist[i] : 0;
    s[t] = v;
    __syncthreads();
    #pragma unroll
    for (int off = 1; off < SCAN_B; off <<= 1) {
        int add = (t >= off) ? s[t - off] : 0;
        __syncthreads();
        s[t] += add;
        __syncthreads();
    }
    if (i < NN) g_off[i] = s[t] - v;            // exclusive
    if (t == SCAN_B - 1) g_bsum[blockIdx.x] = s[t];
}

// scan the 98 block sums (one block)
__global__ void k_scan2() {
    __shared__ int s[128];
    int t = threadIdx.x;
    int v = (t < NBLK) ? g_bsum[t] : 0;
    s[t] = v;
    __syncthreads();
    #pragma unroll
    for (int off = 1; off < 128; off <<= 1) {
        int add = (t >= off) ? s[t - off] : 0;
        __syncthreads();
        s[t] += add;
        __syncthreads();
    }
    if (t < NBLK) g_bsum[t] = s[t] - v;         // exclusive
}

// finalize offsets, cursors, dis
__global__ void k_scan3() {
    int i = blockIdx.x * blockDim.x + threadIdx.x;
    if (i >= NN) return;
    int o = g_off[i] + g_bsum[i >> 10];
    g_off[i] = o;
    g_cursor[i] = o;
    g_dis[i] = rsqrtf(1.0f + (float)g_hist[i]);  // +1 self-loop
    if (i == 0) g_off[NN] = NE;
}

__global__ void k_fill(const int* __restrict__ ei) {
    int e = blockIdx.x * blockDim.x + threadIdx.x;
    if (e >= NE) return;
    int s = ei[e];
    int d = ei[NE + e];
    int pos = atomicAdd(&g_cursor[d], 1);
    g_csr[pos] = s;
}

// ================= dense transforms (dis pre-scaled, fp16 out) =================
// hw = fp16( dis ⊙ (x @ W1) )
__global__ void k_gemm1(const float* __restrict__ x, const float* __restrict__ W1) {
    __shared__ float sW[5 * HD];
    int tid = threadIdx.x;                       // 256
    sW[tid] = W1[tid];
    if (tid < 5 * HD - 256) sW[tid + 256] = W1[tid + 256];
    __syncthreads();
    int node = blockIdx.x * 4 + (tid >> 6);
    int c = tid & 63;
    if (node >= NN) return;
    float acc = 0.f;
    #pragma unroll
    for (int k = 0; k < 5; k++)
        acc += x[node * 5 + k] * sW[k * HD + c];
    g_hw[node * HD + c] = __float2half_rn(acc * g_dis[node]);
}

// hw = fp16( dis ⊙ (h @ W2) ); 16 nodes/block, 4 cols/thread
__global__ void k_gemm2(const float* __restrict__ W2) {
    __shared__ float sW[HD][HD];
    __shared__ float sh[16][HD];
    int tx = threadIdx.x;        // 0..15 (col group)
    int ty = threadIdx.y;        // 0..15 (node)
    int tid = ty * 16 + tx;      // 0..255
    #pragma unroll
    for (int i = 0; i < 16; i++) {
        int idx = tid + i * 256;
        sW[idx >> 6][idx & 63] = W2[idx];
    }
    int node = blockIdx.x * 16 + ty;
    const float* hrow = g_h + (size_t)node * HD;
    #pragma unroll
    for (int i = 0; i < 4; i++)
        sh[ty][tx + i * 16] = (node < NN) ? hrow[tx + i * 16] : 0.f;
    __syncthreads();
    if (node >= NN) return;
    float4 acc = make_float4(0.f, 0.f, 0.f, 0.f);
    #pragma unroll
    for (int k = 0; k < HD; k++) {
        float a = sh[ty][k];
        float4 w = *reinterpret_cast<const float4*>(&sW[k][tx * 4]);
        acc.x += a * w.x; acc.y += a * w.y;
        acc.z += a * w.z; acc.w += a * w.w;
    }
    float dn = g_dis[node];
    __half2 p0 = __floats2half2_rn(acc.x * dn, acc.y * dn);
    __half2 p1 = __floats2half2_rn(acc.z * dn, acc.w * dn);
    uint2 pk = make_uint2(*reinterpret_cast<unsigned*>(&p0),
                          *reinterpret_cast<unsigned*>(&p1));
    *reinterpret_cast<uint2*>(g_hw + (size_t)node * HD + tx * 4) = pk;
}

// hw3 = dis ⊙ (h @ W3); one warp per node (fp32)
__global__ void k_gemm3(const float* __restrict__ W3) {
    __shared__ float sW[HD];
    int tid = threadIdx.x;
    if (tid < HD) sW[tid] = W3[tid];
    __syncthreads();
    int lane = tid & 31;
    int node = blockIdx.x * 8 + (tid >> 5);
    if (node >= NN) return;
    const float* row = g_h + (size_t)node * HD;
    float s = row[lane] * sW[lane] + row[lane + 32] * sW[lane + 32];
    #pragma unroll
    for (int off = 16; off > 0; off >>= 1)
        s += __shfl_down_sync(0xFFFFFFFFu, s, off);
    if (lane == 0) g_hw3[node] = s * g_dis[node];
}

// ================= gather (message passing) =================
// one warp per node; lane owns 2 cols (one half2); fp32 accumulation
__global__ void k_gather64(const float* __restrict__ bias) {
    int lane = threadIdx.x & 31;
    int node = blockIdx.x * 8 + (threadIdx.x >> 5);
    if (node >= NN) return;
    int start = g_off[node];
    int end   = g_off[node + 1];
    const __half2* selfp = reinterpret_cast<const __half2*>(g_hw + (size_t)node * HD) + lane;
    float2 acc = __half22float2(*selfp);          // self-loop term
    for (int base = start; base < end; base += 32) {
        int idx = (base + lane < end) ? g_csr[base + lane] : 0;
        int m = end - base; if (m > 32) m = 32;
        #pragma unroll 4
        for (int j = 0; j < m; j++) {
            int s = __shfl_sync(0xFFFFFFFFu, idx, j);
            const __half2* p = reinterpret_cast<const __half2*>(g_hw + (size_t)s * HD) + lane;
            float2 v = __half22float2(*p);
            acc.x += v.x; acc.y += v.y;
        }
    }
    float dn = g_dis[node];
    float2 r;
    r.x = fmaxf(fmaf(dn, acc.x, bias[2 * lane]), 0.f);
    r.y = fmaxf(fmaf(dn, acc.y, bias[2 * lane + 1]), 0.f);
    *reinterpret_cast<float2*>(g_h + (size_t)node * HD + 2 * lane) = r;
}

// layer 3: one warp per node, lanes stride edges (fp32)
__global__ void k_gather1(float* __restrict__ out, const float* __restrict__ b3) {
    int lane = threadIdx.x & 31;
    int node = blockIdx.x * 8 + (threadIdx.x >> 5);
    if (node >= NN) return;
    int start = g_off[node];
    int end   = g_off[node + 1];
    float acc = 0.f;
    for (int i = start + lane; i < end; i += 32)
        acc += g_hw3[g_csr[i]];
    #pragma unroll
    for (int off = 16; off > 0; off >>= 1)
        acc += __shfl_down_sync(0xFFFFFFFFu, acc, off);
    if (lane == 0)
        out[node] = g_dis[node] * (acc + g_hw3[node]) + b3[0];
}

// ================= launch =================
extern "C" void kernel_launch(void* const* d_in, const int* in_sizes, int n_in,
                              void* d_out, int out_size) {
    const float* x  = (const float*)d_in[0];
    const int*   ei = (const int*)d_in[1];
    const float* W1 = (const float*)d_in[2];
    const float* b1 = (const float*)d_in[3];
    const float* W2 = (const float*)d_in[4];
    const float* b2 = (const float*)d_in[5];
    const float* W3 = (const float*)d_in[6];
    const float* b3 = (const float*)d_in[7];
    float* out = (float*)d_out;

    const int TB = 256;
    // --- CSR + norm build ---
    k_zero_hist<<<(NN + TB - 1) / TB, TB>>>();
    k_hist<<<(NE + TB - 1) / TB, TB>>>(ei);
    k_scan1<<<NBLK, SCAN_B>>>();
    k_scan2<<<1, 128>>>();
    k_scan3<<<(NN + TB - 1) / TB, TB>>>();
    k_fill<<<(NE + TB - 1) / TB, TB>>>(ei);

    // --- layer 1 ---
    k_gemm1<<<(NN + 3) / 4, TB>>>(x, W1);
    k_gather64<<<(NN + 7) / 8, TB>>>(b1);

    // --- layer 2 ---
    k_gemm2<<<(NN + 15) / 16, dim3(16, 16)>>>(W2);
    k_gather64<<<(NN + 7) / 8, TB>>>(b2);

    // --- layer 3 ---
    k_gemm3<<<(NN + 7) / 8, TB>>>(W3);
    k_gather1<<<(NN + 7) / 8, TB>>>(out, b3);
}

// round 6
// speedup vs baseline: 2.1540x; 1.0856x over previous
#include <cuda_runtime.h>
#include <cuda_fp16.h>

#define NN 100000
#define NE 3200000
#define HD 64
#define SCAN_B 1024
#define NBLK ((NN + SCAN_B - 1) / SCAN_B)   // 98
#define CSRMAX (NE + 3 * NN)                // padded CSR capacity

// ---- scratch (__device__ globals; no allocation allowed) ----
__device__ __align__(16) int    g_hist[NN];          // in-degree (excl. self-loop)
__device__ __align__(16) int    g_off[NN + 1];       // padded CSR offsets
__device__ __align__(16) int    g_cursor[NN];        // fill cursors
__device__ __align__(16) int    g_bsum[NBLK];        // scan block sums
__device__ __align__(16) int    g_csr[CSRMAX];       // CSR src lists (padded, sentinel=NN)
__device__ __align__(16) float  g_dis[NN];           // deg^{-1/2}
__device__ __align__(16) float  g_h [NN * HD];       // activations (fp32)
__device__ __align__(16) __half g_hw[(NN + 1) * HD]; // dis*(h@W) fp16; row NN = zeros
__device__ __align__(16) float  g_hw3[NN + 1];       // layer-3 column; [NN] = 0

// ================= graph preprocessing =================
__global__ void k_zero_hist() {
    int i = blockIdx.x * blockDim.x + threadIdx.x;
    if (i < NN) g_hist[i] = 0;
}

__global__ void k_hist(const int* __restrict__ ei) {
    int e = blockIdx.x * blockDim.x + threadIdx.x;
    if (e >= NE) return;
    atomicAdd(&g_hist[ei[NE + e]], 1);
}

// exclusive scan of PADDED degrees ( (deg+3)&~3 ) -> g_off, totals -> g_bsum
__global__ void k_scan1() {
    __shared__ int s[SCAN_B];
    int t = threadIdx.x;
    int i = blockIdx.x * SCAN_B + t;
    int v = (i < NN) ? ((g_hist[i] + 3) & ~3) : 0;
    s[t] = v;
    __syncthreads();
    #pragma unroll
    for (int off = 1; off < SCAN_B; off <<= 1) {
        int add = (t >= off) ? s[t - off] : 0;
        __syncthreads();
        s[t] += add;
        __syncthreads();
    }
    if (i < NN) g_off[i] = s[t] - v;            // exclusive
    if (t == SCAN_B - 1) g_bsum[blockIdx.x] = s[t];
}

__global__ void k_scan2() {
    __shared__ int s[128];
    int t = threadIdx.x;
    int v = (t < NBLK) ? g_bsum[t] : 0;
    s[t] = v;
    __syncthreads();
    #pragma unroll
    for (int off = 1; off < 128; off <<= 1) {
        int add = (t >= off) ? s[t - off] : 0;
        __syncthreads();
        s[t] += add;
        __syncthreads();
    }
    if (t < NBLK) g_bsum[t] = s[t] - v;         // exclusive
}

// finalize offsets, cursors, dis; write sentinel row/entries
__global__ void k_scan3() {
    int i = blockIdx.x * blockDim.x + threadIdx.x;
    if (i >= NN) return;
    int d = g_hist[i];
    int o = g_off[i] + g_bsum[i >> 10];
    g_off[i] = o;
    g_cursor[i] = o;
    g_dis[i] = rsqrtf(1.0f + (float)d);          // +1 self-loop
    if (i == NN - 1) g_off[NN] = o + ((d + 3) & ~3);
    if (i < HD) g_hw[NN * HD + i] = __float2half(0.f);  // zero sentinel row
    if (i == 0) g_hw3[NN] = 0.f;
}

__global__ void k_fill(const int* __restrict__ ei) {
    int e = blockIdx.x * blockDim.x + threadIdx.x;
    if (e >= NE) return;
    int s = ei[e];
    int d = ei[NE + e];
    int pos = atomicAdd(&g_cursor[d], 1);
    g_csr[pos] = s;
}

// pad each node's list to a multiple of 4 with sentinel NN
__global__ void k_pad() {
    int i = blockIdx.x * blockDim.x + threadIdx.x;
    if (i >= NN) return;
    int d = g_hist[i];
    int pd = (d + 3) & ~3;
    int o = g_off[i];
    for (int k = d; k < pd; k++) g_csr[o + k] = NN;
}

// ================= dense transforms (dis pre-scaled, fp16 out) =================
__global__ void k_gemm1(const float* __restrict__ x, const float* __restrict__ W1) {
    __shared__ float sW[5 * HD];
    int tid = threadIdx.x;                       // 256
    sW[tid] = W1[tid];
    if (tid < 5 * HD - 256) sW[tid + 256] = W1[tid + 256];
    __syncthreads();
    int node = blockIdx.x * 4 + (tid >> 6);
    int c = tid & 63;
    if (node >= NN) return;
    float acc = 0.f;
    #pragma unroll
    for (int k = 0; k < 5; k++)
        acc += x[node * 5 + k] * sW[k * HD + c];
    g_hw[node * HD + c] = __float2half_rn(acc * g_dis[node]);
}

__global__ void k_gemm2(const float* __restrict__ W2) {
    __shared__ float sW[HD][HD];
    __shared__ float sh[16][HD];
    int tx = threadIdx.x;        // 0..15
    int ty = threadIdx.y;        // 0..15
    int tid = ty * 16 + tx;      // 0..255
    #pragma unroll
    for (int i = 0; i < 16; i++) {
        int idx = tid + i * 256;
        sW[idx >> 6][idx & 63] = W2[idx];
    }
    int node = blockIdx.x * 16 + ty;
    const float* hrow = g_h + (size_t)node * HD;
    #pragma unroll
    for (int i = 0; i < 4; i++)
        sh[ty][tx + i * 16] = (node < NN) ? hrow[tx + i * 16] : 0.f;
    __syncthreads();
    if (node >= NN) return;
    float4 acc = make_float4(0.f, 0.f, 0.f, 0.f);
    #pragma unroll
    for (int k = 0; k < HD; k++) {
        float a = sh[ty][k];
        float4 w = *reinterpret_cast<const float4*>(&sW[k][tx * 4]);
        acc.x += a * w.x; acc.y += a * w.y;
        acc.z += a * w.z; acc.w += a * w.w;
    }
    float dn = g_dis[node];
    __half2 p0 = __floats2half2_rn(acc.x * dn, acc.y * dn);
    __half2 p1 = __floats2half2_rn(acc.z * dn, acc.w * dn);
    uint2 pk = make_uint2(*reinterpret_cast<unsigned*>(&p0),
                          *reinterpret_cast<unsigned*>(&p1));
    *reinterpret_cast<uint2*>(g_hw + (size_t)node * HD + tx * 4) = pk;
}

__global__ void k_gemm3(const float* __restrict__ W3) {
    __shared__ float sW[HD];
    int tid = threadIdx.x;
    if (tid < HD) sW[tid] = W3[tid];
    __syncthreads();
    int lane = tid & 31;
    int node = blockIdx.x * 8 + (tid >> 5);
    if (node >= NN) return;
    const float* row = g_h + (size_t)node * HD;
    float s = row[lane] * sW[lane] + row[lane + 32] * sW[lane + 32];
    #pragma unroll
    for (int off = 16; off > 0; off >>= 1)
        s += __shfl_down_sync(0xFFFFFFFFu, s, off);
    if (lane == 0) g_hw3[node] = s * g_dis[node];
}

// ================= gather (message passing) =================
// one warp per node; lane = (edge-slot lg 0..3, col-group lc 0..7).
// One LDG.128 fetches 4 edges' 8-col segments; fp32 accumulation.
__global__ void k_gather64(const float* __restrict__ bias) {
    int lane = threadIdx.x & 31;
    int node = blockIdx.x * 8 + (threadIdx.x >> 5);
    if (node >= NN) return;
    int start = g_off[node];
    int pend  = g_off[node + 1];
    int lg = lane >> 3;           // edge slot 0..3
    int lc = lane & 7;            // col group: cols [8*lc, 8*lc+8)

    float acc[8];
    // self-loop row, counted once (group 0 only)
    if (lg == 0) {
        uint4 v = *reinterpret_cast<const uint4*>(g_hw + (size_t)node * HD + lc * 8);
        __half2 h0 = *reinterpret_cast<__half2*>(&v.x);
        __half2 h1 = *reinterpret_cast<__half2*>(&v.y);
        __half2 h2 = *reinterpret_cast<__half2*>(&v.z);
        __half2 h3 = *reinterpret_cast<__half2*>(&v.w);
        float2 f0 = __half22float2(h0), f1 = __half22float2(h1);
        float2 f2 = __half22float2(h2), f3 = __half22float2(h3);
        acc[0] = f0.x; acc[1] = f0.y; acc[2] = f1.x; acc[3] = f1.y;
        acc[4] = f2.x; acc[5] = f2.y; acc[6] = f3.x; acc[7] = f3.y;
    } else {
        #pragma unroll
        for (int k = 0; k < 8; k++) acc[k] = 0.f;
    }

    for (int base = start; base < pend; base += 32) {
        int idx = (base + lane < pend) ? g_csr[base + lane] : NN;
        int m = pend - base; if (m > 32) m = 32;   // m is a multiple of 4
        #pragma unroll 2
        for (int q = 0; q < m; q += 4) {
            int s = __shfl_sync(0xFFFFFFFFu, idx, q + lg);
            uint4 v = *reinterpret_cast<const uint4*>(g_hw + (size_t)s * HD + lc * 8);
            __half2 h0 = *reinterpret_cast<__half2*>(&v.x);
            __half2 h1 = *reinterpret_cast<__half2*>(&v.y);
            __half2 h2 = *reinterpret_cast<__half2*>(&v.z);
            __half2 h3 = *reinterpret_cast<__half2*>(&v.w);
            float2 f0 = __half22float2(h0), f1 = __half22float2(h1);
            float2 f2 = __half22float2(h2), f3 = __half22float2(h3);
            acc[0] += f0.x; acc[1] += f0.y; acc[2] += f1.x; acc[3] += f1.y;
            acc[4] += f2.x; acc[5] += f2.y; acc[6] += f3.x; acc[7] += f3.y;
        }
    }

    // fold the 4 edge-slot groups (lanes lc, lc+8, lc+16, lc+24)
    #pragma unroll
    for (int off = 8; off <= 16; off <<= 1) {
        #pragma unroll
        for (int k = 0; k < 8; k++)
            acc[k] += __shfl_xor_sync(0xFFFFFFFFu, acc[k], off);
    }

    if (lane < 8) {
        float dn = g_dis[node];
        float4 r0, r1;
        r0.x = fmaxf(fmaf(dn, acc[0], bias[lane * 8 + 0]), 0.f);
        r0.y = fmaxf(fmaf(dn, acc[1], bias[lane * 8 + 1]), 0.f);
        r0.z = fmaxf(fmaf(dn, acc[2], bias[lane * 8 + 2]), 0.f);
        r0.w = fmaxf(fmaf(dn, acc[3], bias[lane * 8 + 3]), 0.f);
        r1.x = fmaxf(fmaf(dn, acc[4], bias[lane * 8 + 4]), 0.f);
        r1.y = fmaxf(fmaf(dn, acc[5], bias[lane * 8 + 5]), 0.f);
        r1.z = fmaxf(fmaf(dn, acc[6], bias[lane * 8 + 6]), 0.f);
        r1.w = fmaxf(fmaf(dn, acc[7], bias[lane * 8 + 7]), 0.f);
        float* o = g_h + (size_t)node * HD + lane * 8;
        *reinterpret_cast<float4*>(o)     = r0;
        *reinterpret_cast<float4*>(o + 4) = r1;
    }
}

// layer 3: one warp per node, lanes stride edges (sentinel reads 0)
__global__ void k_gather1(float* __restrict__ out, const float* __restrict__ b3) {
    int lane = threadIdx.x & 31;
    int node = blockIdx.x * 8 + (threadIdx.x >> 5);
    if (node >= NN) return;
    int start = g_off[node];
    int end   = g_off[node + 1];
    float acc = 0.f;
    for (int i = start + lane; i < end; i += 32)
        acc += g_hw3[g_csr[i]];
    #pragma unroll
    for (int off = 16; off > 0; off >>= 1)
        acc += __shfl_down_sync(0xFFFFFFFFu, acc, off);
    if (lane == 0)
        out[node] = g_dis[node] * (acc + g_hw3[node]) + b3[0];
}

// ================= launch =================
extern "C" void kernel_launch(void* const* d_in, const int* in_sizes, int n_in,
                              void* d_out, int out_size) {
    const float* x  = (const float*)d_in[0];
    const int*   ei = (const int*)d_in[1];
    const float* W1 = (const float*)d_in[2];
    const float* b1 = (const float*)d_in[3];
    const float* W2 = (const float*)d_in[4];
    const float* b2 = (const float*)d_in[5];
    const float* W3 = (const float*)d_in[6];
    const float* b3 = (const float*)d_in[7];
    float* out = (float*)d_out;

    const int TB = 256;
    // --- CSR + norm build ---
    k_zero_hist<<<(NN + TB - 1) / TB, TB>>>();
    k_hist<<<(NE + TB - 1) / TB, TB>>>(ei);
    k_scan1<<<NBLK, SCAN_B>>>();
    k_scan2<<<1, 128>>>();
    k_scan3<<<(NN + TB - 1) / TB, TB>>>();
    k_fill<<<(NE + TB - 1) / TB, TB>>>(ei);
    k_pad<<<(NN + TB - 1) / TB, TB>>>();

    // --- layer 1 ---
    k_gemm1<<<(NN + 3) / 4, TB>>>(x, W1);
    k_gather64<<<(NN + 7) / 8, TB>>>(b1);

    // --- layer 2 ---
    k_gemm2<<<(NN + 15) / 16, dim3(16, 16)>>>(W2);
    k_gather64<<<(NN + 7) / 8, TB>>>(b2);

    // --- layer 3 ---
    k_gemm3<<<(NN + 7) / 8, TB>>>(W3);
    k_gather1<<<(NN + 7) / 8, TB>>>(out, b3);
}